// round 16
// baseline (speedup 1.0000x reference)
#include <cuda_runtime.h>
#include <cuda_bf16.h>

// out[b] = sum_k x[b,k] * |W[k]| * fc1_w[k] + fc1_b
// B=32, K = T*P = 4,000,000
//
// Converged design (14 rounds of ncu-driven search):
//  - batch-per-block, 27 column groups -> grid 864 ~= 148 SM * 6 CTA
//  - 6 CTAs/SM is the measured occupancy optimum (DRAM%: 4/SM=77, 6/SM=85,
//    8/SM=79 -- 8/SM loses to cross-CTA L1tex queue contention)
//  - x (512 MB, read-once) streamed with __ldcs (evict-first);
//    W/F (32 MB) default-cached, L2-shared across 32 co-resident batch-blocks
//  - separate trivial init kernel: fused finalize costs +4..9 us
//    (gpu-scope fence/atomic -> CCTL.IVALL L1 flush storm)
#define NBATCH  32
#define TP      4000000
#define NVEC    (TP / 4)      // 1,000,000 float4 per batch row
#define GROUPS  27            // column groups -> grid 864 ~= 148 SM * 6 CTA
#define THREADS 256
#define STRIDE  (GROUPS * THREADS)   // 6912 float4 per sweep

__global__ void init_out_kernel(const float* __restrict__ fc1_b,
                                float* __restrict__ out) {
    out[threadIdx.x] = fc1_b[0];
}

__global__ __launch_bounds__(THREADS, 6)   // cap regs at 42 -> 6 CTAs/SM
void dot_kernel(const float4* __restrict__ x,
                const float4* __restrict__ W,
                const float4* __restrict__ F,
                float* __restrict__ out) {
    const int b   = blockIdx.x & (NBATCH - 1);   // batch (fastest-varying)
    const int g   = blockIdx.x >> 5;             // column group 0..26
    const int tid = threadIdx.x;

    const float4* __restrict__ xb = x + (size_t)b * NVEC;

    float a0 = 0.f, a1 = 0.f, a2 = 0.f, a3 = 0.f;

    // unroll 2 (not 4): keeps live float4 count at 6 -> 40 regs, no spills
#pragma unroll 2
    for (int j = g * THREADS + tid; j < NVEC; j += STRIDE) {
        // x: read-once stream -> evict-first so it can't thrash W/F in L2
        float4 xv = __ldcs(&xb[j]);
        // W/F: shared across the 32 co-resident batch-blocks -> L2 hits
        float4 w = __ldg(&W[j]);
        float4 f = __ldg(&F[j]);
        a0 = fmaf(xv.x, fabsf(w.x) * f.x, a0);
        a1 = fmaf(xv.y, fabsf(w.y) * f.y, a1);
        a2 = fmaf(xv.z, fabsf(w.z) * f.z, a2);
        a3 = fmaf(xv.w, fabsf(w.w) * f.w, a3);
    }

    float v = (a0 + a1) + (a2 + a3);

    // ---- block reduction: warp shfl -> smem -> single atomic ----
    __shared__ float sred[THREADS / 32];
    const int lane = tid & 31;
    const int wrp  = tid >> 5;

#pragma unroll
    for (int off = 16; off; off >>= 1)
        v += __shfl_xor_sync(0xffffffffu, v, off);
    if (lane == 0) sred[wrp] = v;
    __syncthreads();

    if (wrp == 0) {
        float s = (lane < THREADS / 32) ? sred[lane] : 0.f;
#pragma unroll
        for (int off = 4; off; off >>= 1)
            s += __shfl_xor_sync(0xffffffffu, s, off);
        if (lane == 0) atomicAdd(&out[b], s);
    }
}

extern "C" void kernel_launch(void* const* d_in, const int* in_sizes, int n_in,
                              void* d_out, int out_size) {
    const float4* x  = (const float4*)d_in[0];  // [32, 4M]
    const float4* W  = (const float4*)d_in[1];  // [4M]
    const float4* F  = (const float4*)d_in[2];  // fc1_w [4M]
    const float*  bb = (const float*)d_in[3];   // fc1_b [1]
    float* out = (float*)d_out;                 // [32]

    (void)in_sizes; (void)n_in; (void)out_size;

    init_out_kernel<<<1, NBATCH>>>(bb, out);
    dot_kernel<<<NBATCH * GROUPS, THREADS>>>(x, W, F, out);
}